// round 5
// baseline (speedup 1.0000x reference)
#include <cuda_runtime.h>
#include <cuda_bf16.h>

// RBFSetConv separable: per batch C(192x64) = A^T(192x4096) @ B(4096x64)
//   A = [wx | y*wx | t*wx] (mask folded), B = wy, w = exp(-50 d^2).
// Split-K over 37 CTAs/batch -> private transposed partial tiles [gy][row],
// k_fin reduces (coalesced both ways) and finalizes.
// Weights via multiplicative recurrence (3 ex2 per 8-col segment).
// Inner loop: A plain fp32 (row-pairs via LDS.128), B duplicated u64
// (col-dups via LDS.128), FFMA2 packed accumulation, double-buffered smem.

#define B_      8
#define N_      4096
#define GR      64
#define SPLITS  37
#define CTAS    (B_ * SPLITS)        // 296 = 2 CTAs/SM
#define CHUNK   16
#define NCHUNKS (N_ / CHUNK)         // 256

#define APITCHF 196                  // floats per point row of A (784B, 16B-mult)
#define BPITCHU 66                   // u64 per point row of B   (528B, 16B-mult)
#define TILE    (GR * 192)           // 12288 floats per partial tile

#define DEL 0.031746032f             // 2/63
#define ALG 72.134752f               // 50*log2(e)
#define C1C 4.579985f                // 100*DEL*log2(e)
#define C2C (-0.0727013f)            // -50*DEL^2*log2(e)
#define QF  0.90413095f              // exp(-100*DEL^2)

__device__ float g_part[CTAS * TILE];   // 14.5 MB scratch

typedef unsigned long long ull;

__device__ __forceinline__ float ex2f(float x) {
    float r; asm("ex2.approx.ftz.f32 %0, %1;" : "=f"(r) : "f"(x)); return r;
}
__device__ __forceinline__ void ffma2(ull& d, ull a, ull b) {
    asm("fma.rn.f32x2 %0, %1, %2, %0;" : "+l"(d) : "l"(a), "l"(b));
}
__device__ __forceinline__ ull dup32(float v) {
    unsigned u = __float_as_uint(v);
    return (ull)u | ((ull)u << 32);
}
__device__ __forceinline__ void chk1(unsigned v, int& bi, int& bf, int& bh) {
    bi |= (v > 1u);
    bf |= (v != 0u && v != 0x3F800000u);
    unsigned lo = v & 0xFFFFu, hi = v >> 16;
    bh |= (lo != 0u && lo != 0x3F80u) || (hi != 0u && hi != 0x3F80u);
}

__global__ void __launch_bounds__(256, 2)
k_main(const float* __restrict__ xc, const float* __restrict__ yc,
       const float* __restrict__ tc, const void* __restrict__ mask) {
    __shared__ __align__(16) float sA[2][CHUNK * APITCHF];  // 2 x 12544 B
    __shared__ __align__(16) ull   sB[2][CHUNK * BPITCHU];  // 2 x  8448 B
    __shared__ int smode;

    const int tid = threadIdx.x;
    const int b   = blockIdx.x / SPLITS;
    const int s   = blockIdx.x % SPLITS;

    // ---- mask dtype detection (bitwise, 1KB sample, warp 0) ----
    if (tid < 32) {
        const int4* mv = (const int4*)mask;
        int4 a = __ldg(mv + tid);
        int4 c = __ldg(mv + tid + 32);
        int bi = 0, bf = 0, bh = 0;
        chk1((unsigned)a.x, bi, bf, bh); chk1((unsigned)a.y, bi, bf, bh);
        chk1((unsigned)a.z, bi, bf, bh); chk1((unsigned)a.w, bi, bf, bh);
        chk1((unsigned)c.x, bi, bf, bh); chk1((unsigned)c.y, bi, bf, bh);
        chk1((unsigned)c.z, bi, bf, bh); chk1((unsigned)c.w, bi, bf, bh);
        bi = __any_sync(0xFFFFFFFFu, bi);
        bf = __any_sync(0xFFFFFFFFu, bf);
        bh = __any_sync(0xFFFFFFFFu, bh);
        if (tid == 0) smode = (!bi) ? 0 : (!bf) ? 1 : (!bh) ? 2 : 3;
    }
    __syncthreads();
    const int mode = smode;

    // prep mapping: threads 0-127 -> wx (3 ch), 128-255 -> wy. 16 pts x 8 segs.
    const bool is_wx = (tid < 128);
    const int  tt  = is_wx ? tid : tid - 128;
    const int  p   = tt >> 3;          // point 0..15
    const int  seg = tt & 7;           // 8-column segment
    const int  lo  = seg * 8, hi = lo + 7;

    // mma mapping: 16 col-threads x 16 row-threads
    const int col_t = tid & 15;        // 4 gy-cols each
    const int row_t = tid >> 4;        // 12 rows (6 pairs) each

    ull acc[6][4];
#pragma unroll
    for (int r = 0; r < 6; r++)
#pragma unroll
        for (int c = 0; c < 4; c++) acc[r][c] = 0ull;

    // my chunk list: s, s+37, ... (7 for s<34, else 6)
    int cis[7], nc = 0;
    for (int ci = s; ci < NCHUNKS; ci += SPLITS) cis[nc++] = ci;

    // ---------------- prep one chunk into buffer bi ----------------
    auto prep = [&](int ci, int bi) {
        const int gi = b * N_ + ci * CHUNK + p;
        float2 pt = ((const float2*)xc)[gi];
        float x = is_wx ? pt.x : pt.y;

        float fi = (x + 1.0f) * 31.5f;
        int kc = __float2int_rn(fi);
        kc = min(max(kc, lo), hi);
        float d   = x - (-1.0f + (float)kc * DEL);
        float w0  = ex2f(-ALG * d * d);
        float rup = ex2f( C1C * d + C2C);
        float rdn = ex2f(-C1C * d + C2C);

        if (is_wx) {
            float yv = yc[gi], tv = tc[gi];
            float vm;
            if (mode == 0)      vm = (((const int*)mask)[gi] != 0) ? 0.0f : 1.0f;
            else if (mode == 1) vm = (((const unsigned*)mask)[gi] != 0u) ? 0.0f : 1.0f;
            else if (mode == 2) vm = ((((const unsigned short*)mask)[gi]) != 0) ? 0.0f : 1.0f;
            else                vm = (((const unsigned char*)mask)[gi] != 0) ? 0.0f : 1.0f;
            w0 *= vm;

            float* a0 = &sA[bi][p * APITCHF];
            float w = w0, r = rup;
#pragma unroll
            for (int j = 0; j < 8; j++) {
                int k = kc + j;
                if (k <= hi) { a0[k] = w; a0[64 + k] = yv * w; a0[128 + k] = tv * w; }
                w *= r; r *= QF;
            }
            w = w0; r = rdn;
#pragma unroll
            for (int j = 1; j < 8; j++) {
                w *= r; r *= QF;
                int k = kc - j;
                if (k >= lo) { a0[k] = w; a0[64 + k] = yv * w; a0[128 + k] = tv * w; }
            }
        } else {
            ull* b0 = &sB[bi][p * BPITCHU];
            float w = w0, r = rup;
#pragma unroll
            for (int j = 0; j < 8; j++) {
                int k = kc + j;
                if (k <= hi) b0[k] = dup32(w);
                w *= r; r *= QF;
            }
            w = w0; r = rdn;
#pragma unroll
            for (int j = 1; j < 8; j++) {
                w *= r; r *= QF;
                int k = kc - j;
                if (k >= lo) b0[k] = dup32(w);
            }
        }
    };

    // ---------------- rank-16 FFMA2 update from buffer bi ----------------
    auto mma = [&](int bi) {
        const float* __restrict__ A  = sA[bi];
        const ull*   __restrict__ Bp = sB[bi];
#pragma unroll 4
        for (int pp = 0; pp < CHUNK; pp++) {
            const ull* aa = (const ull*)(A + pp * APITCHF + 12 * row_t);
            ulonglong2 a01 = *(const ulonglong2*)(aa);
            ulonglong2 a23 = *(const ulonglong2*)(aa + 2);
            ulonglong2 a45 = *(const ulonglong2*)(aa + 4);
            const ull* bb = Bp + pp * BPITCHU + 4 * col_t;
            ulonglong2 b01 = *(const ulonglong2*)(bb);
            ulonglong2 b23 = *(const ulonglong2*)(bb + 2);
            ull av[6] = {a01.x, a01.y, a23.x, a23.y, a45.x, a45.y};
            ull bv[4] = {b01.x, b01.y, b23.x, b23.y};
#pragma unroll
            for (int rp = 0; rp < 6; rp++) {
                ffma2(acc[rp][0], av[rp], bv[0]);
                ffma2(acc[rp][1], av[rp], bv[1]);
                ffma2(acc[rp][2], av[rp], bv[2]);
                ffma2(acc[rp][3], av[rp], bv[3]);
            }
        }
    };

    prep(cis[0], 0);
    __syncthreads();
    for (int k = 0; k < nc; k++) {
        if (k + 1 < nc) prep(cis[k + 1], (k + 1) & 1);  // overlaps with mma(k)
        mma(k & 1);
        __syncthreads();
    }

    // ---- flush private partial tile, transposed [gy][row], STG.64 ----
    ull* pu = (ull*)(g_part + (size_t)blockIdx.x * TILE);
#pragma unroll
    for (int rp = 0; rp < 6; rp++)
#pragma unroll
        for (int c = 0; c < 4; c++)
            pu[(4 * col_t + c) * 96 + 6 * row_t + rp] = acc[rp][c];
}

// Reduce 37 partials per batch + finalize. Tile layout: [gy][ch*64+gx].
// Block (b, gy=i): 192 threads = (ch, gx=j). Reads & writes fully coalesced.
__global__ void k_fin(float* __restrict__ out) {
    __shared__ float sinv[GR];
    const int bid = blockIdx.x;
    const int b   = bid >> 6;
    const int i   = bid & 63;
    const int tid = threadIdx.x;        // ch*64 + j
    const int ch  = tid >> 6;
    const int j   = tid & 63;

    const float* base = g_part + ((size_t)b * SPLITS) * TILE + i * 192 + tid;
    float sum = 0.0f;
#pragma unroll
    for (int s = 0; s < SPLITS; s++)
        sum += __ldg(base + s * TILE);

    if (ch == 0) sinv[j] = 1.0f / (sum + 1e-5f);
    __syncthreads();

    float v = (ch == 0) ? sum : sum * sinv[j];
    out[b * 3 * 4096 + ch * 4096 + i * 64 + j] = v;
}

extern "C" void kernel_launch(void* const* d_in, const int* in_sizes, int n_in,
                              void* d_out, int out_size) {
    const float* xc   = (const float*)d_in[0];
    const float* yc   = (const float*)d_in[1];
    const float* tc   = (const float*)d_in[2];
    const void*  mask = d_in[3];

    k_main<<<CTAS, 256>>>(xc, yc, tc, mask);
    k_fin<<<B_ * GR, 192>>>((float*)d_out);
}

// round 11
// speedup vs baseline: 1.5628x; 1.5628x over previous
#include <cuda_runtime.h>
#include <cuda_bf16.h>
#include <cstdint>

// RBFSetConv separable: per batch C^T(64x192) = Wy(64x4096) @ P(4096x192),
//   P = [wx | y*wx | t*wx] (mask folded into wx), Wy = wy, w = exp(-50 d^2).
// Tensor path: mma.sync.m16n8k8 tf32 with 3-product error compensation:
//   C = Ah@Bh + Al@Bh + Ah@Bl      (Al@Bl ~ 2^-24, dropped)
// 256 CTAs = 8 batches x 32 K-splits, 128 points each, 4 chunks of 32.
// Partial tiles -> g_part; last 128 CTAs (monotonic ticket) reduce+finalize.

typedef unsigned long long ull;

#define SPLITS 32
#define CTAS   256
#define TILE   12288                // 64 x 192 floats per partial tile

// smem float offsets
#define AH 0                        // wy hi: [64 gy][pitch 36]
#define AL 2304
#define BH 4608                     // P  hi: [32 k][pitch 200]
#define BL 11008
#define SMEM_FLOATS 17408           // 69632 bytes

#define DEL   0.031746032f          // 2/63
#define ALG   72.134752f            // 50*log2(e)
#define C1C8  36.639880f            // 8 * 100*DEL*log2(e)
#define C2C64 (-4.6528896f)         // 64 * (-50*DEL^2*log2(e))

__device__ float    g_part[CTAS * TILE];   // 12.6 MB scratch
__device__ unsigned g_ctr;                 // monotonic ticket counter

__device__ __forceinline__ float ex2f(float x) {
    float r; asm("ex2.approx.ftz.f32 %0, %1;" : "=f"(r) : "f"(x)); return r;
}
__device__ __forceinline__ float tf32hi(float v) {
    float h; asm("cvt.rna.tf32.f32 %0, %1;" : "=f"(h) : "f"(v)); return h;
}
__device__ __forceinline__ void mma8(float* d, const unsigned* a, const unsigned* b) {
    asm volatile(
        "mma.sync.aligned.m16n8k8.row.col.f32.tf32.tf32.f32 "
        "{%0,%1,%2,%3}, {%4,%5,%6,%7}, {%8,%9}, {%0,%1,%2,%3};"
        : "+f"(d[0]), "+f"(d[1]), "+f"(d[2]), "+f"(d[3])
        : "r"(a[0]), "r"(a[1]), "r"(a[2]), "r"(a[3]), "r"(b[0]), "r"(b[1]));
}
__device__ __forceinline__ void chk1(unsigned v, int& bi, int& bf, int& bh) {
    bi |= (v > 1u);
    bf |= (v != 0u && v != 0x3F800000u);
    unsigned lo = v & 0xFFFFu, hi = v >> 16;
    bh |= (lo != 0u && lo != 0x3F80u) || (hi != 0u && hi != 0x3F80u);
}

__global__ void __launch_bounds__(256, 2)
k_all(const float* __restrict__ xc, const float* __restrict__ yc,
      const float* __restrict__ tc, const void* __restrict__ mask,
      float* __restrict__ out) {
    extern __shared__ float sd[];
    __shared__ int   s_mode;
    __shared__ unsigned s_ticket;
    __shared__ float s_inv[64];

    const int tid = threadIdx.x;
    const int l   = tid & 31;
    const int w   = tid >> 5;
    const int b   = blockIdx.x >> 5;
    const int s   = blockIdx.x & 31;

    // ---- mask dtype detection (bitwise, 1KB sample, warp 0) ----
    if (tid < 32) {
        const int4* mv = (const int4*)mask;
        int4 a = __ldg(mv + tid);
        int4 c = __ldg(mv + tid + 32);
        int bi = 0, bf = 0, bh = 0;
        chk1((unsigned)a.x, bi, bf, bh); chk1((unsigned)a.y, bi, bf, bh);
        chk1((unsigned)a.z, bi, bf, bh); chk1((unsigned)a.w, bi, bf, bh);
        chk1((unsigned)c.x, bi, bf, bh); chk1((unsigned)c.y, bi, bf, bh);
        chk1((unsigned)c.z, bi, bf, bh); chk1((unsigned)c.w, bi, bf, bh);
        bi = __any_sync(0xFFFFFFFFu, bi);
        bf = __any_sync(0xFFFFFFFFu, bf);
        bh = __any_sync(0xFFFFFFFFu, bh);
        if (tid == 0) s_mode = (!bi) ? 0 : (!bf) ? 1 : (!bh) ? 2 : 3;
    }
    __syncthreads();
    const int mode = s_mode;
    const float Q8 = ex2f(2.0f * C2C64);   // QF^64

    // prep mapping: point p (0..31) x segment seg (0..7); cols = seg + 8j
    const int p   = tid >> 3;
    const int seg = tid & 7;

    float acc[4][3][4];
#pragma unroll
    for (int mb = 0; mb < 4; mb++)
#pragma unroll
        for (int i = 0; i < 3; i++)
#pragma unroll
            for (int q = 0; q < 4; q++) acc[mb][i][q] = 0.0f;

    for (int c = 0; c < 4; c++) {
        // ================= prep chunk c (32 points) =================
        {
            const int gi = b * 4096 + s * 128 + c * 32 + p;
            float2 pt = ((const float2*)xc)[gi];
            float yv = yc[gi], tv = tc[gi];
            float vm;
            if (mode == 0)      vm = (((const int*)mask)[gi] != 0) ? 0.0f : 1.0f;
            else if (mode == 1) vm = (((const unsigned*)mask)[gi] != 0u) ? 0.0f : 1.0f;
            else if (mode == 2) vm = ((((const unsigned short*)mask)[gi]) != 0) ? 0.0f : 1.0f;
            else                vm = (((const unsigned char*)mask)[gi] != 0) ? 0.0f : 1.0f;

            // ---- wx -> B rows: Bh/Bl[p][{gx, 64+gx, 128+gx}] ----
            {
                float x  = pt.x;
                float jf = ((x + 1.0f) * 31.5f - (float)seg) * 0.125f;
                int jc = __float2int_rn(jf);
                jc = max(0, min(7, jc));
                float d0  = x + 1.0f - (float)(seg + 8 * jc) * DEL;
                float w0  = ex2f(-ALG * d0 * d0) * vm;
                float rup = ex2f( C1C8 * d0 + C2C64);
                float rdn = ex2f(-C1C8 * d0 + C2C64);
                float wv = w0, r = rup;
#pragma unroll
                for (int jj = 0; jj < 8; jj++) {
                    int j = jc + jj;
                    if (j < 8) {
                        int idx = p * 200 + seg + 8 * j;
                        float v1 = wv, v2 = yv * wv, v3 = tv * wv;
                        float h1 = tf32hi(v1), h2 = tf32hi(v2), h3 = tf32hi(v3);
                        sd[BH + idx]       = h1;  sd[BL + idx]       = v1 - h1;
                        sd[BH + idx + 64]  = h2;  sd[BL + idx + 64]  = v2 - h2;
                        sd[BH + idx + 128] = h3;  sd[BL + idx + 128] = v3 - h3;
                    }
                    wv *= r; r *= Q8;
                }
                wv = w0; r = rdn;
#pragma unroll
                for (int jj = 1; jj < 8; jj++) {
                    wv *= r; r *= Q8;
                    int j = jc - jj;
                    if (j >= 0) {
                        int idx = p * 200 + seg + 8 * j;
                        float v1 = wv, v2 = yv * wv, v3 = tv * wv;
                        float h1 = tf32hi(v1), h2 = tf32hi(v2), h3 = tf32hi(v3);
                        sd[BH + idx]       = h1;  sd[BL + idx]       = v1 - h1;
                        sd[BH + idx + 64]  = h2;  sd[BL + idx + 64]  = v2 - h2;
                        sd[BH + idx + 128] = h3;  sd[BL + idx + 128] = v3 - h3;
                    }
                }
            }
            // ---- wy -> A rows: Ah/Al[gy][p] ----
            {
                float x  = pt.y;
                float jf = ((x + 1.0f) * 31.5f - (float)seg) * 0.125f;
                int jc = __float2int_rn(jf);
                jc = max(0, min(7, jc));
                float d0  = x + 1.0f - (float)(seg + 8 * jc) * DEL;
                float w0  = ex2f(-ALG * d0 * d0);
                float rup = ex2f( C1C8 * d0 + C2C64);
                float rdn = ex2f(-C1C8 * d0 + C2C64);
                float wv = w0, r = rup;
#pragma unroll
                for (int jj = 0; jj < 8; jj++) {
                    int j = jc + jj;
                    if (j < 8) {
                        int idx = (seg + 8 * j) * 36 + p;
                        float h = tf32hi(wv);
                        sd[AH + idx] = h;  sd[AL + idx] = wv - h;
                    }
                    wv *= r; r *= Q8;
                }
                wv = w0; r = rdn;
#pragma unroll
                for (int jj = 1; jj < 8; jj++) {
                    wv *= r; r *= Q8;
                    int j = jc - jj;
                    if (j >= 0) {
                        int idx = (seg + 8 * j) * 36 + p;
                        float h = tf32hi(wv);
                        sd[AH + idx] = h;  sd[AL + idx] = wv - h;
                    }
                }
            }
        }
        __syncthreads();

        // ================= mma: 4 ksteps of k8 =================
#pragma unroll
        for (int ks = 0; ks < 4; ks++) {
            const int k0 = ks * 8;
            unsigned ah[4][4], al[4][4], bh[3][2], bl[3][2];
            const int abase = (l >> 2) * 36 + k0 + (l & 3);
#pragma unroll
            for (int mb = 0; mb < 4; mb++) {
                int o = abase + mb * (16 * 36);
                ah[mb][0] = __float_as_uint(sd[AH + o]);
                ah[mb][1] = __float_as_uint(sd[AH + o + 8 * 36]);
                ah[mb][2] = __float_as_uint(sd[AH + o + 4]);
                ah[mb][3] = __float_as_uint(sd[AH + o + 8 * 36 + 4]);
                al[mb][0] = __float_as_uint(sd[AL + o]);
                al[mb][1] = __float_as_uint(sd[AL + o + 8 * 36]);
                al[mb][2] = __float_as_uint(sd[AL + o + 4]);
                al[mb][3] = __float_as_uint(sd[AL + o + 8 * 36 + 4]);
            }
            const int bbase = (k0 + (l & 3)) * 200 + (l >> 2);
#pragma unroll
            for (int i = 0; i < 3; i++) {
                int o = bbase + (3 * w + i) * 8;
                bh[i][0] = __float_as_uint(sd[BH + o]);
                bh[i][1] = __float_as_uint(sd[BH + o + 4 * 200]);
                bl[i][0] = __float_as_uint(sd[BL + o]);
                bl[i][1] = __float_as_uint(sd[BL + o + 4 * 200]);
            }
#pragma unroll
            for (int mb = 0; mb < 4; mb++)
#pragma unroll
                for (int i = 0; i < 3; i++) {
                    mma8(acc[mb][i], ah[mb], bh[i]);
                    mma8(acc[mb][i], al[mb], bh[i]);
                    mma8(acc[mb][i], ah[mb], bl[i]);
                }
        }
        __syncthreads();
    }

    // ================= flush partial tile [gy][192] =================
    {
        float* dst = g_part + (size_t)blockIdx.x * TILE;
#pragma unroll
        for (int mb = 0; mb < 4; mb++)
#pragma unroll
            for (int i = 0; i < 3; i++) {
                int gy = mb * 16 + (l >> 2);
                int n  = (3 * w + i) * 8 + 2 * (l & 3);
                *(float2*)(dst + gy * 192 + n) =
                    make_float2(acc[mb][i][0], acc[mb][i][1]);
                *(float2*)(dst + (gy + 8) * 192 + n) =
                    make_float2(acc[mb][i][2], acc[mb][i][3]);
            }
    }

    // ================= ticket: last 128 CTAs reduce + finalize ==========
    __threadfence();
    __syncthreads();
    if (tid == 0) s_ticket = atomicAdd(&g_ctr, 1u);
    __syncthreads();
    const unsigned tk = s_ticket;
    const unsigned rr = tk & 255u;            // base is a multiple of 256
    if (rr < 128u) return;

    if (tid == 0) {
        const unsigned target = ((tk >> 8) + 1u) << 8;
        while (atomicAdd(&g_ctr, 0u) < target) { }
    }
    __syncthreads();
    __threadfence();

    const int ru = (int)(rr - 128u);          // 0..127, 4 (b,gy) units each
#pragma unroll 1
    for (int jj = 0; jj < 4; jj++) {
        int u   = ru * 4 + jj;
        int ub  = u >> 6, ugy = u & 63;
        float sum = 0.0f;
        if (tid < 192) {
            const float* base = g_part + ((size_t)(ub * SPLITS)) * TILE + ugy * 192 + tid;
#pragma unroll
            for (int sp = 0; sp < SPLITS; sp++)
                sum += base[sp * TILE];
            if (tid < 64) s_inv[tid] = 1.0f / (sum + 1e-5f);
        }
        __syncthreads();
        if (tid < 192) {
            int ch = tid >> 6, gx = tid & 63;
            float v = (ch == 0) ? sum : sum * s_inv[gx];
            out[((ub * 3 + ch) << 12) + (ugy << 6) + gx] = v;
        }
        __syncthreads();
    }
}

extern "C" void kernel_launch(void* const* d_in, const int* in_sizes, int n_in,
                              void* d_out, int out_size) {
    const float* xc   = (const float*)d_in[0];
    const float* yc   = (const float*)d_in[1];
    const float* tc   = (const float*)d_in[2];
    const void*  mask = d_in[3];

    static int smem_set = 0;
    if (!smem_set) {
        cudaFuncSetAttribute(k_all, cudaFuncAttributeMaxDynamicSharedMemorySize,
                             SMEM_FLOATS * 4);
        smem_set = 1;
    }
    k_all<<<CTAS, 256, SMEM_FLOATS * 4>>>(xc, yc, tc, mask, (float*)d_out);
}